// round 7
// baseline (speedup 1.0000x reference)
#include <cuda_runtime.h>

#define N_NODES 500000
#define N_EDGES 4000000

// ---- scratch (device globals; no allocation allowed) ----
__device__ int    g_cnt[N_NODES];    // self-restoring: k_prep zeroes after reading
__device__ float4 g_y[N_NODES];      // {dinv*x0, dinv*x1, dinv*x2, dinv} (gather source)
__device__ float  g_dinv[N_NODES];   // dense dinv for coalesced node-kernel reads
__device__ float4 g_agg1[N_NODES];   // accumulated neighbor sums (xyz used, w junk)
__device__ float  g_s[N_NODES];      // dinv * (relu(h1) @ W2)
__device__ float  g_agg2[N_NODES];

// ---- K1: degree count over edge targets (int4, 4 edges/thread) ----
// No grid-dependency sync needed: touches only col (input) and g_cnt, neither of
// which conflicts with the stream predecessor (k_final: g_dinv/g_agg2/out).
__global__ void __launch_bounds__(256) k_count(const int* __restrict__ col) {
    int i = blockIdx.x * blockDim.x + threadIdx.x;
    if (i < N_EDGES / 4) {
        int4 c = reinterpret_cast<const int4*>(col)[i];
        atomicAdd(&g_cnt[c.x], 1);
        atomicAdd(&g_cnt[c.y], 1);
        atomicAdd(&g_cnt[c.z], 1);
        atomicAdd(&g_cnt[c.w], 1);
    }
}

// ---- K2: dinv = rsqrt(deg), y = dinv*x, agg1 init, and reset g_cnt for next call ----
__global__ void __launch_bounds__(256) k_prep(const float* __restrict__ x) {
    int v = blockIdx.x * blockDim.x + threadIdx.x;
    // prologue: input-only loads, may overlap k_count
    float x0 = 0.f, x1 = 0.f, x2 = 0.f;
    if (v < N_NODES) {
        x0 = x[3 * v + 0];
        x1 = x[3 * v + 1];
        x2 = x[3 * v + 2];
    }
    cudaGridDependencySynchronize();  // wait for k_count's atomics
    if (v < N_NODES) {
        int cnt = g_cnt[v];
        g_cnt[v] = 0;                         // restore for next graph replay
        float d = rsqrtf((float)(cnt + 1));   // +1 self-loop
        float4 y = make_float4(d * x0, d * x1, d * x2, d);
        g_y[v]    = y;  // gather source
        g_agg1[v] = y;  // self-loop term pre-seeded
        g_dinv[v] = d;  // dense copy
    }
}

// ---- K3: edge scatter, layer 1: one float4 atomic per edge (4 edges/thread) ----
__global__ void __launch_bounds__(256) k_scatter1(const int* __restrict__ row,
                                                  const int* __restrict__ col) {
    int i = blockIdx.x * blockDim.x + threadIdx.x;
    int4 r = make_int4(0, 0, 0, 0), c = make_int4(0, 0, 0, 0);
    bool act = i < N_EDGES / 4;
    if (act) {  // prologue: index loads overlap k_prep
        r = reinterpret_cast<const int4*>(row)[i];
        c = reinterpret_cast<const int4*>(col)[i];
    }
    cudaGridDependencySynchronize();  // wait for g_y / g_agg1
    if (act) {
        atomicAdd(&g_agg1[c.x], g_y[r.x]);
        atomicAdd(&g_agg1[c.y], g_y[r.y]);
        atomicAdd(&g_agg1[c.z], g_y[r.z]);
        atomicAdd(&g_agg1[c.w], g_y[r.w]);
    }
}

// ---- K4: fused node MLP: h1 = relu((dinv*agg1) @ W1 + b1); s = dinv*(h1 @ W2) ----
__global__ void __launch_bounds__(256) k_mlp(const float* __restrict__ W1,
                                             const float* __restrict__ b1,
                                             const float* __restrict__ W2) {
    __shared__ float sW1[48];  // [3][16] row-major
    __shared__ float sb1[16];
    __shared__ float sW2[16];
    int t = threadIdx.x;
    if (t < 48) sW1[t] = W1[t];            // prologue: input-only
    if (t < 16) { sb1[t] = b1[t]; sW2[t] = W2[t]; }
    __syncthreads();
    cudaGridDependencySynchronize();  // wait for k_scatter1's atomics
    int v = blockIdx.x * blockDim.x + t;
    if (v < N_NODES) {
        float4 a = g_agg1[v];
        float  d = g_dinv[v];
        float t0 = d * a.x, t1 = d * a.y, t2 = d * a.z;
        float acc = 0.0f;
#pragma unroll
        for (int j = 0; j < 16; j++) {
            float h = fmaf(t0, sW1[j],
                      fmaf(t1, sW1[16 + j],
                      fmaf(t2, sW1[32 + j], sb1[j])));
            acc = fmaf(fmaxf(h, 0.0f), sW2[j], acc);
        }
        float s = d * acc;
        g_s[v]    = s;  // gather source for layer 2
        g_agg2[v] = s;  // self-loop term included
    }
}

// ---- K5: edge scatter, layer 2 (scalar), 4 edges/thread ----
__global__ void __launch_bounds__(256) k_scatter2(const int* __restrict__ row,
                                                  const int* __restrict__ col) {
    int i = blockIdx.x * blockDim.x + threadIdx.x;
    int4 r = make_int4(0, 0, 0, 0), c = make_int4(0, 0, 0, 0);
    bool act = i < N_EDGES / 4;
    if (act) {  // prologue: index loads overlap k_mlp
        r = reinterpret_cast<const int4*>(row)[i];
        c = reinterpret_cast<const int4*>(col)[i];
    }
    cudaGridDependencySynchronize();  // wait for g_s / g_agg2
    if (act) {
        atomicAdd(&g_agg2[c.x], g_s[r.x]);
        atomicAdd(&g_agg2[c.y], g_s[r.y]);
        atomicAdd(&g_agg2[c.z], g_s[r.z]);
        atomicAdd(&g_agg2[c.w], g_s[r.w]);
    }
}

// ---- K6: finalize: out = dinv*agg2 + b2 ----
__global__ void __launch_bounds__(256) k_final(float* __restrict__ out,
                                               const float* __restrict__ b2) {
    float bias = b2[0];  // prologue: input-only
    cudaGridDependencySynchronize();  // wait for k_scatter2's atomics
    int v = blockIdx.x * blockDim.x + threadIdx.x;
    if (v < N_NODES) {
        out[v] = fmaf(g_dinv[v], g_agg2[v], bias);
    }
}

template <typename... Args>
static inline void launch_pdl(void (*kern)(Args...), int grid, int block, Args... args) {
    cudaLaunchConfig_t cfg = {};
    cfg.gridDim = dim3(grid, 1, 1);
    cfg.blockDim = dim3(block, 1, 1);
    cudaLaunchAttribute attr[1];
    attr[0].id = cudaLaunchAttributeProgrammaticStreamSerialization;
    attr[0].val.programmaticStreamSerializationAllowed = 1;
    cfg.attrs = attr;
    cfg.numAttrs = 1;
    cudaLaunchKernelEx(&cfg, kern, args...);
}

extern "C" void kernel_launch(void* const* d_in, const int* in_sizes, int n_in,
                              void* d_out, int out_size) {
    const float* x   = (const float*)d_in[0];
    const int*   ei  = (const int*)d_in[1];   // [2][E]: row = ei, col = ei + E
    const float* W1  = (const float*)d_in[2]; // [3][16]
    const float* b1  = (const float*)d_in[3]; // [16]
    const float* W2  = (const float*)d_in[4]; // [16][1]
    const float* b2  = (const float*)d_in[5]; // [1]
    float* out = (float*)d_out;

    const int* row = ei;
    const int* col = ei + N_EDGES;

    const int T = 256;
    const int nb_nodes = (N_NODES + T - 1) / T;
    const int nb_e4    = (N_EDGES / 4 + T - 1) / T;

    launch_pdl(k_count, nb_e4, T, col);
    launch_pdl(k_prep, nb_nodes, T, x);
    launch_pdl(k_scatter1, nb_e4, T, row, col);
    launch_pdl(k_mlp, nb_nodes, T, W1, b1, W2);
    launch_pdl(k_scatter2, nb_e4, T, row, col);
    launch_pdl(k_final, nb_nodes, T, out, b2);
}

// round 8
// speedup vs baseline: 1.0140x; 1.0140x over previous
#include <cuda_runtime.h>

#define N_NODES 500000
#define N_EDGES 4000000

// ---- scratch (device globals; no allocation allowed) ----
__device__ int    g_cnt[N_NODES];    // zero-initialized; k_prep re-zeroes after reading
__device__ float4 g_y[N_NODES];      // {dinv*x0, dinv*x1, dinv*x2, dinv} (gather source)
__device__ float  g_dinv[N_NODES];   // dense dinv for coalesced node-kernel reads
__device__ float4 g_agg1[N_NODES];   // accumulated neighbor sums (xyz used, w junk)
__device__ float  g_s[N_NODES];      // dinv * (relu(h1) @ W2)
__device__ float  g_agg2[N_NODES];

// ---- K1: degree count over edge targets (int4, 4 edges/thread) ----
__global__ void __launch_bounds__(256) k_count(const int* __restrict__ col) {
    int i = blockIdx.x * blockDim.x + threadIdx.x;
    if (i < N_EDGES / 4) {
        int4 c = reinterpret_cast<const int4*>(col)[i];
        atomicAdd(&g_cnt[c.x], 1);
        atomicAdd(&g_cnt[c.y], 1);
        atomicAdd(&g_cnt[c.z], 1);
        atomicAdd(&g_cnt[c.w], 1);
    }
}

// ---- K2: dinv = rsqrt(deg), y = dinv*x, agg1 init; zeroes g_cnt for next call ----
__global__ void __launch_bounds__(256) k_prep(const float* __restrict__ x) {
    int v = blockIdx.x * blockDim.x + threadIdx.x;
    if (v < N_NODES) {
        int cnt = g_cnt[v];
        g_cnt[v] = 0;                         // self-restore: next call starts from zero
        float d = rsqrtf((float)(cnt + 1));   // +1 self-loop
        float x0 = x[3 * v + 0];
        float x1 = x[3 * v + 1];
        float x2 = x[3 * v + 2];
        float4 y = make_float4(d * x0, d * x1, d * x2, d);
        g_y[v]    = y;  // gather source
        g_agg1[v] = y;  // self-loop term pre-seeded
        g_dinv[v] = d;  // dense copy for coalesced reads downstream
    }
}

// ---- K3: edge scatter, layer 1: one float4 atomic per edge (4 edges/thread) ----
__global__ void __launch_bounds__(256) k_scatter1(const int* __restrict__ row,
                                                  const int* __restrict__ col) {
    int i = blockIdx.x * blockDim.x + threadIdx.x;
    if (i < N_EDGES / 4) {
        int4 r = reinterpret_cast<const int4*>(row)[i];
        int4 c = reinterpret_cast<const int4*>(col)[i];
        atomicAdd(&g_agg1[c.x], g_y[r.x]);
        atomicAdd(&g_agg1[c.y], g_y[r.y]);
        atomicAdd(&g_agg1[c.z], g_y[r.z]);
        atomicAdd(&g_agg1[c.w], g_y[r.w]);
    }
}

// ---- K4: fused node MLP: h1 = relu((dinv*agg1) @ W1 + b1); s = dinv*(h1 @ W2) ----
__global__ void __launch_bounds__(256) k_mlp(const float* __restrict__ W1,
                                             const float* __restrict__ b1,
                                             const float* __restrict__ W2) {
    __shared__ float sW1[48];  // [3][16] row-major
    __shared__ float sb1[16];
    __shared__ float sW2[16];
    int t = threadIdx.x;
    if (t < 48) sW1[t] = W1[t];
    if (t < 16) { sb1[t] = b1[t]; sW2[t] = W2[t]; }
    __syncthreads();

    int v = blockIdx.x * blockDim.x + t;
    if (v < N_NODES) {
        float4 a = g_agg1[v];
        float  d = g_dinv[v];
        float t0 = d * a.x, t1 = d * a.y, t2 = d * a.z;
        float acc = 0.0f;
#pragma unroll
        for (int j = 0; j < 16; j++) {
            float h = fmaf(t0, sW1[j],
                      fmaf(t1, sW1[16 + j],
                      fmaf(t2, sW1[32 + j], sb1[j])));
            acc = fmaf(fmaxf(h, 0.0f), sW2[j], acc);
        }
        float s = d * acc;
        g_s[v]    = s;  // gather source for layer 2
        g_agg2[v] = s;  // self-loop term included
    }
}

// ---- K5: edge scatter, layer 2 (scalar), 4 edges/thread ----
__global__ void __launch_bounds__(256) k_scatter2(const int* __restrict__ row,
                                                  const int* __restrict__ col) {
    int i = blockIdx.x * blockDim.x + threadIdx.x;
    if (i < N_EDGES / 4) {
        int4 r = reinterpret_cast<const int4*>(row)[i];
        int4 c = reinterpret_cast<const int4*>(col)[i];
        atomicAdd(&g_agg2[c.x], g_s[r.x]);
        atomicAdd(&g_agg2[c.y], g_s[r.y]);
        atomicAdd(&g_agg2[c.z], g_s[r.z]);
        atomicAdd(&g_agg2[c.w], g_s[r.w]);
    }
}

// ---- K6: finalize: out = dinv*agg2 + b2 ----
__global__ void __launch_bounds__(256) k_final(float* __restrict__ out,
                                               const float* __restrict__ b2) {
    int v = blockIdx.x * blockDim.x + threadIdx.x;
    if (v < N_NODES) {
        out[v] = fmaf(g_dinv[v], g_agg2[v], b2[0]);
    }
}

extern "C" void kernel_launch(void* const* d_in, const int* in_sizes, int n_in,
                              void* d_out, int out_size) {
    const float* x   = (const float*)d_in[0];
    const int*   ei  = (const int*)d_in[1];   // [2][E]: row = ei, col = ei + E
    const float* W1  = (const float*)d_in[2]; // [3][16]
    const float* b1  = (const float*)d_in[3]; // [16]
    const float* W2  = (const float*)d_in[4]; // [16][1]
    const float* b2  = (const float*)d_in[5]; // [1]
    float* out = (float*)d_out;

    const int* row = ei;
    const int* col = ei + N_EDGES;

    const int T = 256;
    const int nb_nodes = (N_NODES + T - 1) / T;
    const int nb_e4    = (N_EDGES / 4 + T - 1) / T;

    k_count<<<nb_e4, T>>>(col);
    k_prep<<<nb_nodes, T>>>(x);
    k_scatter1<<<nb_e4, T>>>(row, col);
    k_mlp<<<nb_nodes, T>>>(W1, b1, W2);
    k_scatter2<<<nb_e4, T>>>(row, col);
    k_final<<<nb_nodes, T>>>(out, b2);
}

// round 9
// speedup vs baseline: 1.0209x; 1.0067x over previous
#include <cuda_runtime.h>

#define N_NODES 500000
#define N_EDGES 4000000

// ---- scratch (device globals; no allocation allowed) ----
__device__ int    g_cnt[N_NODES];
__device__ float4 g_y[N_NODES];      // {dinv*x0, dinv*x1, dinv*x2, dinv} (gather source)
__device__ float  g_dinv[N_NODES];   // dense dinv for coalesced node-kernel reads
__device__ float4 g_agg1[N_NODES];   // accumulated neighbor sums (xyz used, w junk)
__device__ float  g_s[N_NODES];      // dinv * (relu(h1) @ W2)
__device__ float  g_agg2[N_NODES];

// ---- K0: zero degree counters (also L2-warms g_cnt for k_count's atomics) ----
__global__ void __launch_bounds__(256) k_zero_cnt() {
    int i = blockIdx.x * blockDim.x + threadIdx.x;
    if (i < N_NODES) g_cnt[i] = 0;
}

// ---- K1: degree count over edge targets (int4, 4 edges/thread) ----
__global__ void __launch_bounds__(256) k_count(const int* __restrict__ col) {
    int i = blockIdx.x * blockDim.x + threadIdx.x;
    if (i < N_EDGES / 4) {
        int4 c = reinterpret_cast<const int4*>(col)[i];
        atomicAdd(&g_cnt[c.x], 1);
        atomicAdd(&g_cnt[c.y], 1);
        atomicAdd(&g_cnt[c.z], 1);
        atomicAdd(&g_cnt[c.w], 1);
    }
}

// ---- K2: dinv = rsqrt(deg), y = dinv*x, agg1 init = self-loop term ----
__global__ void __launch_bounds__(256) k_prep(const float* __restrict__ x) {
    int v = blockIdx.x * blockDim.x + threadIdx.x;
    if (v < N_NODES) {
        float d = rsqrtf((float)(g_cnt[v] + 1));  // +1 self-loop
        float x0 = x[3 * v + 0];
        float x1 = x[3 * v + 1];
        float x2 = x[3 * v + 2];
        float4 y = make_float4(d * x0, d * x1, d * x2, d);
        g_y[v]    = y;  // gather source
        g_agg1[v] = y;  // self-loop term pre-seeded
        g_dinv[v] = d;  // dense copy for coalesced reads downstream
    }
}

// ---- K3: edge scatter, layer 1: one float4 atomic per edge (4 edges/thread) ----
__global__ void __launch_bounds__(256) k_scatter1(const int* __restrict__ row,
                                                  const int* __restrict__ col) {
    int i = blockIdx.x * blockDim.x + threadIdx.x;
    if (i < N_EDGES / 4) {
        int4 r = reinterpret_cast<const int4*>(row)[i];
        int4 c = reinterpret_cast<const int4*>(col)[i];
        atomicAdd(&g_agg1[c.x], g_y[r.x]);
        atomicAdd(&g_agg1[c.y], g_y[r.y]);
        atomicAdd(&g_agg1[c.z], g_y[r.z]);
        atomicAdd(&g_agg1[c.w], g_y[r.w]);
    }
}

// ---- K4: fused node MLP, 2 nodes/thread ----
// h1 = relu((dinv*agg1) @ W1 + b1); s = dinv*(h1 @ W2)
__global__ void __launch_bounds__(256) k_mlp(const float* __restrict__ W1,
                                             const float* __restrict__ b1,
                                             const float* __restrict__ W2) {
    __shared__ float sW1[48];  // [3][16] row-major
    __shared__ float sb1[16];
    __shared__ float sW2[16];
    int t = threadIdx.x;
    if (t < 48) sW1[t] = W1[t];
    if (t < 16) { sb1[t] = b1[t]; sW2[t] = W2[t]; }
    __syncthreads();

    int base = blockIdx.x * 512;
    int va = base + t;          // node A
    int vb = base + 256 + t;    // node B (coalesced second wave)

    float a0 = 0.f, a1 = 0.f, a2 = 0.f, da = 0.f;
    float c0 = 0.f, c1 = 0.f, c2 = 0.f, db = 0.f;
    bool actA = va < N_NODES, actB = vb < N_NODES;
    if (actA) {
        float4 a = g_agg1[va];
        da = g_dinv[va];
        a0 = da * a.x; a1 = da * a.y; a2 = da * a.z;
    }
    if (actB) {
        float4 c = g_agg1[vb];
        db = g_dinv[vb];
        c0 = db * c.x; c1 = db * c.y; c2 = db * c.z;
    }

    float accA = 0.0f, accB = 0.0f;
#pragma unroll
    for (int j = 0; j < 16; j++) {
        float w0 = sW1[j], w1 = sW1[16 + j], w2 = sW1[32 + j];
        float bb = sb1[j], w2o = sW2[j];
        float hA = fmaf(a0, w0, fmaf(a1, w1, fmaf(a2, w2, bb)));
        float hB = fmaf(c0, w0, fmaf(c1, w1, fmaf(c2, w2, bb)));
        accA = fmaf(fmaxf(hA, 0.0f), w2o, accA);
        accB = fmaf(fmaxf(hB, 0.0f), w2o, accB);
    }
    if (actA) {
        float s = da * accA;
        g_s[va] = s;  g_agg2[va] = s;
    }
    if (actB) {
        float s = db * accB;
        g_s[vb] = s;  g_agg2[vb] = s;
    }
}

// ---- K5: edge scatter, layer 2 (scalar), 4 edges/thread ----
__global__ void __launch_bounds__(256) k_scatter2(const int* __restrict__ row,
                                                  const int* __restrict__ col) {
    int i = blockIdx.x * blockDim.x + threadIdx.x;
    if (i < N_EDGES / 4) {
        int4 r = reinterpret_cast<const int4*>(row)[i];
        int4 c = reinterpret_cast<const int4*>(col)[i];
        atomicAdd(&g_agg2[c.x], g_s[r.x]);
        atomicAdd(&g_agg2[c.y], g_s[r.y]);
        atomicAdd(&g_agg2[c.z], g_s[r.z]);
        atomicAdd(&g_agg2[c.w], g_s[r.w]);
    }
}

// ---- K6: finalize: out = dinv*agg2 + b2, 4 nodes/thread (float4) ----
__global__ void __launch_bounds__(256) k_final(float* __restrict__ out,
                                               const float* __restrict__ b2) {
    int q = blockIdx.x * blockDim.x + threadIdx.x;
    if (q < N_NODES / 4) {
        float bias = b2[0];
        float4 d = reinterpret_cast<const float4*>(g_dinv)[q];
        float4 a = reinterpret_cast<const float4*>(g_agg2)[q];
        float4 o;
        o.x = fmaf(d.x, a.x, bias);
        o.y = fmaf(d.y, a.y, bias);
        o.z = fmaf(d.z, a.z, bias);
        o.w = fmaf(d.w, a.w, bias);
        reinterpret_cast<float4*>(out)[q] = o;
    }
}

extern "C" void kernel_launch(void* const* d_in, const int* in_sizes, int n_in,
                              void* d_out, int out_size) {
    const float* x   = (const float*)d_in[0];
    const int*   ei  = (const int*)d_in[1];   // [2][E]: row = ei, col = ei + E
    const float* W1  = (const float*)d_in[2]; // [3][16]
    const float* b1  = (const float*)d_in[3]; // [16]
    const float* W2  = (const float*)d_in[4]; // [16][1]
    const float* b2  = (const float*)d_in[5]; // [1]
    float* out = (float*)d_out;

    const int* row = ei;
    const int* col = ei + N_EDGES;

    const int T = 256;
    const int nb_nodes  = (N_NODES + T - 1) / T;
    const int nb_nodes2 = (N_NODES + 2 * T - 1) / (2 * T);
    const int nb_quads  = (N_NODES / 4 + T - 1) / T;
    const int nb_e4     = (N_EDGES / 4 + T - 1) / T;

    k_zero_cnt<<<nb_nodes, T>>>();
    k_count<<<nb_e4, T>>>(col);
    k_prep<<<nb_nodes, T>>>(x);
    k_scatter1<<<nb_e4, T>>>(row, col);
    k_mlp<<<nb_nodes2, T>>>(W1, b1, W2);
    k_scatter2<<<nb_e4, T>>>(row, col);
    k_final<<<nb_quads, T>>>(out, b2);
}

// round 10
// speedup vs baseline: 1.0495x; 1.0280x over previous
#include <cuda_runtime.h>

#define N_NODES 500000
#define N_EDGES 4000000

// ---- scratch (device globals; no allocation allowed) ----
// Invariant: g_cnt == 0 at every kernel_launch entry (zero-init at load;
// k_final re-zeroes it at the end of every call).
__device__ int    g_cnt[N_NODES];
__device__ float4 g_y[N_NODES];      // {dinv*x0, dinv*x1, dinv*x2, dinv} (gather source)
__device__ float  g_dinv[N_NODES];   // dense dinv for coalesced node-kernel reads
__device__ float4 g_agg1[N_NODES];   // accumulated neighbor sums (xyz used, w junk)
__device__ float  g_s[N_NODES];      // dinv * (relu(h1) @ W2)
__device__ float  g_agg2[N_NODES];

// ---- K1: degree count over edge targets (int4, 4 edges/thread) ----
__global__ void __launch_bounds__(256) k_count(const int* __restrict__ col) {
    int i = blockIdx.x * blockDim.x + threadIdx.x;
    if (i < N_EDGES / 4) {
        int4 c = reinterpret_cast<const int4*>(col)[i];
        atomicAdd(&g_cnt[c.x], 1);
        atomicAdd(&g_cnt[c.y], 1);
        atomicAdd(&g_cnt[c.z], 1);
        atomicAdd(&g_cnt[c.w], 1);
    }
}

// ---- K2: dinv = rsqrt(deg), y = dinv*x, agg1 init = self-loop term ----
__global__ void __launch_bounds__(256) k_prep(const float* __restrict__ x) {
    int v = blockIdx.x * blockDim.x + threadIdx.x;
    if (v < N_NODES) {
        float d = rsqrtf((float)(g_cnt[v] + 1));  // +1 self-loop
        float x0 = x[3 * v + 0];
        float x1 = x[3 * v + 1];
        float x2 = x[3 * v + 2];
        float4 y = make_float4(d * x0, d * x1, d * x2, d);
        g_y[v]    = y;  // gather source
        g_agg1[v] = y;  // self-loop term pre-seeded
        g_dinv[v] = d;  // dense copy for coalesced reads downstream
    }
}

// ---- K3: edge scatter, layer 1: one float4 atomic per edge (4 edges/thread) ----
__global__ void __launch_bounds__(256) k_scatter1(const int* __restrict__ row,
                                                  const int* __restrict__ col) {
    int i = blockIdx.x * blockDim.x + threadIdx.x;
    if (i < N_EDGES / 4) {
        int4 r = reinterpret_cast<const int4*>(row)[i];
        int4 c = reinterpret_cast<const int4*>(col)[i];
        atomicAdd(&g_agg1[c.x], g_y[r.x]);
        atomicAdd(&g_agg1[c.y], g_y[r.y]);
        atomicAdd(&g_agg1[c.z], g_y[r.z]);
        atomicAdd(&g_agg1[c.w], g_y[r.w]);
    }
}

// ---- K4: fused node MLP: h1 = relu((dinv*agg1) @ W1 + b1); s = dinv*(h1 @ W2) ----
__global__ void __launch_bounds__(256) k_mlp(const float* __restrict__ W1,
                                             const float* __restrict__ b1,
                                             const float* __restrict__ W2) {
    __shared__ float sW1[48];  // [3][16] row-major
    __shared__ float sb1[16];
    __shared__ float sW2[16];
    int t = threadIdx.x;
    if (t < 48) sW1[t] = W1[t];
    if (t < 16) { sb1[t] = b1[t]; sW2[t] = W2[t]; }
    __syncthreads();

    int v = blockIdx.x * blockDim.x + t;
    if (v < N_NODES) {
        float4 a = g_agg1[v];
        float  d = g_dinv[v];
        float t0 = d * a.x, t1 = d * a.y, t2 = d * a.z;
        float acc = 0.0f;
#pragma unroll
        for (int j = 0; j < 16; j++) {
            float h = fmaf(t0, sW1[j],
                      fmaf(t1, sW1[16 + j],
                      fmaf(t2, sW1[32 + j], sb1[j])));
            acc = fmaf(fmaxf(h, 0.0f), sW2[j], acc);
        }
        float s = d * acc;
        g_s[v]    = s;  // gather source for layer 2
        g_agg2[v] = s;  // self-loop term included
    }
}

// ---- K5: edge scatter, layer 2 (scalar), 4 edges/thread ----
__global__ void __launch_bounds__(256) k_scatter2(const int* __restrict__ row,
                                                  const int* __restrict__ col) {
    int i = blockIdx.x * blockDim.x + threadIdx.x;
    if (i < N_EDGES / 4) {
        int4 r = reinterpret_cast<const int4*>(row)[i];
        int4 c = reinterpret_cast<const int4*>(col)[i];
        atomicAdd(&g_agg2[c.x], g_s[r.x]);
        atomicAdd(&g_agg2[c.y], g_s[r.y]);
        atomicAdd(&g_agg2[c.z], g_s[r.z]);
        atomicAdd(&g_agg2[c.w], g_s[r.w]);
    }
}

// ---- K6: finalize: out = dinv*agg2 + b2; also zeroes g_cnt for the next call ----
// The g_cnt sweep at the END of the call keeps g_cnt L2-resident for the next
// replay's k_count atomics (the warming role k_zero_cnt used to play), while
// deleting one kernel launch + one standalone pass.
__global__ void __launch_bounds__(256) k_final(float* __restrict__ out,
                                               const float* __restrict__ b2) {
    int v = blockIdx.x * blockDim.x + threadIdx.x;
    if (v < N_NODES) {
        out[v] = fmaf(g_dinv[v], g_agg2[v], b2[0]);
        g_cnt[v] = 0;  // restore invariant for next call; L2-warms for next k_count
    }
}

extern "C" void kernel_launch(void* const* d_in, const int* in_sizes, int n_in,
                              void* d_out, int out_size) {
    const float* x   = (const float*)d_in[0];
    const int*   ei  = (const int*)d_in[1];   // [2][E]: row = ei, col = ei + E
    const float* W1  = (const float*)d_in[2]; // [3][16]
    const float* b1  = (const float*)d_in[3]; // [16]
    const float* W2  = (const float*)d_in[4]; // [16][1]
    const float* b2  = (const float*)d_in[5]; // [1]
    float* out = (float*)d_out;

    const int* row = ei;
    const int* col = ei + N_EDGES;

    const int T = 256;
    const int nb_nodes = (N_NODES + T - 1) / T;
    const int nb_e4    = (N_EDGES / 4 + T - 1) / T;

    k_count<<<nb_e4, T>>>(col);
    k_prep<<<nb_nodes, T>>>(x);
    k_scatter1<<<nb_e4, T>>>(row, col);
    k_mlp<<<nb_nodes, T>>>(W1, b1, W2);
    k_scatter2<<<nb_e4, T>>>(row, col);
    k_final<<<nb_nodes, T>>>(out, b2);
}